// round 14
// baseline (speedup 1.0000x reference)
#include <cuda_runtime.h>
#include <cuda_bf16.h>
#include <cstdint>

#define B_SZ 2048
#define T_SZ 256
#define IN_SZ 65
#define H_SZ 64
#define BR 16
#define NTH 256

typedef unsigned int u32;

// ---- smem layout (bytes) ----
#define AST 272                          // A row stride: 136 bf16 (16B-mult, LDSM conflict-free)
#define BST 272                          // hx row stride
#define OFF_AH 0                         // A hi  [256][AST]
#define OFF_AL (OFF_AH + 256 * AST)      // 69632: A lo
#define OFF_B  (OFF_AL + 256 * AST)      // 139264: hx [par][split][16][BST]
#define BSECT  (16 * BST)                // 4352
#define OFF_X64 (OFF_B + 4 * BSECT)      // 156672: x64 [par][16] float
#define OFF_HFIN (OFF_X64 + 2 * 16 * 4)  // 156800: hfin [16][68] float
#define SMEM_TOTAL (OFF_HFIN + 16 * 68 * 4)  // 161152

__device__ __forceinline__ u32 smem_u32(const void* p) {
    u32 a;
    asm("{ .reg .u64 t; cvta.to.shared.u64 t, %1; cvt.u32.u64 %0, t; }" : "=r"(a) : "l"(p));
    return a;
}
__device__ __forceinline__ void ldsm4(u32& r0, u32& r1, u32& r2, u32& r3, u32 addr) {
    asm volatile("ldmatrix.sync.aligned.m8n8.x4.shared.b16 {%0,%1,%2,%3}, [%4];"
                 : "=r"(r0), "=r"(r1), "=r"(r2), "=r"(r3) : "r"(addr));
}
__device__ __forceinline__ void mma16816(float* d, const u32* a, u32 b0, u32 b1) {
    asm volatile("mma.sync.aligned.m16n8k16.row.col.f32.bf16.bf16.f32 "
                 "{%0,%1,%2,%3}, {%4,%5,%6,%7}, {%8,%9}, {%0,%1,%2,%3};"
                 : "+f"(d[0]), "+f"(d[1]), "+f"(d[2]), "+f"(d[3])
                 : "r"(a[0]), "r"(a[1]), "r"(a[2]), "r"(a[3]), "r"(b0), "r"(b1));
}
__device__ __forceinline__ float ex2f(float x) { float y; asm("ex2.approx.f32 %0, %1;" : "=f"(y) : "f"(x)); return y; }
__device__ __forceinline__ float rcpf(float x) { float y; asm("rcp.approx.f32 %0, %1;" : "=f"(y) : "f"(x)); return y; }
__device__ __forceinline__ float sigf(float x) { return rcpf(1.0f + ex2f(-1.4426950408889634f * x)); }
__device__ __forceinline__ float tanhf_(float x) { return fmaf(2.0f, rcpf(1.0f + ex2f(-2.8853900817779268f * x)), -1.0f); }

__global__ __launch_bounds__(NTH, 1)
void lstm_mma_kernel(const float* __restrict__ x,
                     const float* __restrict__ Wih,
                     const float* __restrict__ Whh,
                     const float* __restrict__ bih,
                     const float* __restrict__ bhh,
                     const float* __restrict__ fcW,
                     const float* __restrict__ fcb,
                     float* __restrict__ out) {
    extern __shared__ char sm[];
    const u32 smb = smem_u32(sm);
    const int tid = threadIdx.x;
    const int wid = tid >> 5;
    const int lane = tid & 31;
    const int b0 = blockIdx.x * BR;

    // ---- one-time: W -> A tiles (split bf16). A row g, col k: k<64 = Whh, 64..127 = Wih[:,0:64]
    for (int idx = tid; idx < 256 * 128; idx += NTH) {
        int g = idx >> 7, k = idx & 127;
        float v = (k < 64) ? Whh[g * 64 + k] : Wih[g * 65 + (k - 64)];
        __nv_bfloat16 hi = __float2bfloat16(v);
        __nv_bfloat16 lo = __float2bfloat16(v - __bfloat162float(hi));
        *(__nv_bfloat16*)(sm + OFF_AH + g * AST + k * 2) = hi;
        *(__nv_bfloat16*)(sm + OFF_AL + g * AST + k * 2) = lo;
    }
    // zero hx buffers (h(-1)=0, padding) + x64
    for (int idx = tid; idx < (4 * BSECT) / 4; idx += NTH) ((u32*)(sm + OFF_B))[idx] = 0;
    if (tid < 32) ((float*)(sm + OFF_X64))[tid] = 0.0f;

    // ---- x-stream slots: 16 rows x 65 feats = 1040 -> 5 slots/thread
    const float* xptr[5]; int xn[5], xf[5]; bool xok[5];
#pragma unroll
    for (int m = 0; m < 5; ++m) {
        int idx = tid + m * NTH;
        xok[m] = idx < 16 * IN_SZ;
        int n = xok[m] ? idx / IN_SZ : 0;
        int f = xok[m] ? idx - n * IN_SZ : 0;
        xn[m] = n; xf[m] = f;
        xptr[m] = x + ((size_t)(b0 + n) * T_SZ) * IN_SZ + f;
    }
    __syncthreads();
    // x(0) -> parity 0
#pragma unroll
    for (int m = 0; m < 5; ++m) {
        if (xok[m]) {
            float v = *xptr[m];
            xptr[m] += IN_SZ;
            if (xf[m] == 64) ((float*)(sm + OFF_X64))[xn[m]] = v;
            else {
                __nv_bfloat16 hi = __float2bfloat16(v);
                __nv_bfloat16 lo = __float2bfloat16(v - __bfloat162float(hi));
                char* bp = sm + OFF_B + xn[m] * BST + (64 + xf[m]) * 2;
                *(__nv_bfloat16*)bp = hi;
                *(__nv_bfloat16*)(bp + BSECT) = lo;
            }
        }
    }

    // ---- roles: warp w -> units 16*(w&3)..+15 (all 4 gate groups), batches (w>>2)*8..+7
    const int wq = wid & 3;
    const int nb = (wid >> 2) * 8;
    const int r = lane >> 2;
    const int u0 = wq * 16 + r, u1 = u0 + 8;
    const int c0 = nb + 2 * (lane & 3), c1 = c0 + 1;

    float bias[8], w64r[8];
#pragma unroll
    for (int G = 0; G < 4; ++G) {
        int ga = G * 64 + u0, gb_ = G * 64 + u1;
        bias[G * 2] = bih[ga] + bhh[ga];
        bias[G * 2 + 1] = bih[gb_] + bhh[gb_];
        w64r[G * 2] = Wih[ga * 65 + 64];
        w64r[G * 2 + 1] = Wih[gb_ * 65 + 64];
    }
    float cst[4] = {0.f, 0.f, 0.f, 0.f};   // cells (u0,c0),(u0,c1),(u1,c0),(u1,c1)

    // ldmatrix base: + split-offset + G*64*AST + kt*32
    const u32 aBase = smb + (wq * 16 + (lane & 15)) * AST + (lane >> 4) * 16;
    // B frag base: row n = nb + lane/4, k-byte = (lane%4)*4 ; + par/split + kt*32 (b1 at +16)
    const u32 bBase = smb + OFF_B + (nb + (lane >> 2)) * BST + (lane & 3) * 4;

    __syncthreads();

    for (int t = 0; t < T_SZ; ++t) {
        const int par = t & 1, nxt = par ^ 1;
        const bool hasNext = (t + 1 < T_SZ);

        // ---- load B fragments (hx hi/lo) for this parity ----
        u32 bh[16], bl[16];
        {
            const char* ph = (const char*)sm + (bBase - smb) + par * 2 * BSECT;
#pragma unroll
            for (int kt = 0; kt < 8; ++kt) {
                bh[2 * kt]     = *(const u32*)(ph + kt * 32);
                bh[2 * kt + 1] = *(const u32*)(ph + kt * 32 + 16);
                bl[2 * kt]     = *(const u32*)(ph + BSECT + kt * 32);
                bl[2 * kt + 1] = *(const u32*)(ph + BSECT + kt * 32 + 16);
            }
        }
        // ---- prefetch x(t+1) ----
        float xv[5];
#pragma unroll
        for (int m = 0; m < 5; ++m) xv[m] = (hasNext && xok[m]) ? *xptr[m] : 0.f;
        // x64 for this step
        const float xs0 = ((float*)(sm + OFF_X64))[par * 16 + c0];
        const float xs1 = ((float*)(sm + OFF_X64))[par * 16 + c1];

        // ---- MMA: kt outer, G inner; 3 separate accumulator sets to break
        //      the dependency chains (depth 24 -> 8; 12 independent chains) ----
        float D[4][4], E[4][4], F[4][4];
#pragma unroll
        for (int G = 0; G < 4; ++G) {
#pragma unroll
            for (int q = 0; q < 4; ++q) { D[G][q] = 0.f; E[G][q] = 0.f; F[G][q] = 0.f; }
        }
#pragma unroll
        for (int kt = 0; kt < 8; ++kt) {
            const u32 bh0 = bh[2 * kt], bh1 = bh[2 * kt + 1];
            const u32 bl0 = bl[2 * kt], bl1 = bl[2 * kt + 1];
#pragma unroll
            for (int G = 0; G < 4; ++G) {
                u32 ah[4], al[4];
                ldsm4(ah[0], ah[1], ah[2], ah[3], aBase + OFF_AH + G * 64 * AST + kt * 32);
                ldsm4(al[0], al[1], al[2], al[3], aBase + OFF_AL + G * 64 * AST + kt * 32);
                mma16816(D[G], ah, bh0, bh1);
                mma16816(E[G], ah, bl0, bl1);
                mma16816(F[G], al, bh0, bh1);
            }
        }

        // ---- update (in registers): cells q: 0=(u0,c0) 1=(u0,c1) 2=(u1,c0) 3=(u1,c1) ----
#pragma unroll
        for (int q = 0; q < 4; ++q) {
            const int uu = (q >> 1);              // 0: u0 rows, 1: u1 rows
            const float xs = (q & 1) ? xs1 : xs0;
            const int cc = (q & 1) ? c1 : c0;
            const int un = uu ? u1 : u0;
            float gi = (D[0][q] + E[0][q] + F[0][q]) + fmaf(w64r[0 + uu], xs, bias[0 + uu]);
            float gf = (D[1][q] + E[1][q] + F[1][q]) + fmaf(w64r[2 + uu], xs, bias[2 + uu]);
            float gg = (D[2][q] + E[2][q] + F[2][q]) + fmaf(w64r[4 + uu], xs, bias[4 + uu]);
            float go = (D[3][q] + E[3][q] + F[3][q]) + fmaf(w64r[6 + uu], xs, bias[6 + uu]);
            float iv = sigf(gi), fv = sigf(gf), gv = tanhf_(gg), ov = sigf(go);
            cst[q] = fv * cst[q] + iv * gv;
            float h = ov * tanhf_(cst[q]);
            // h -> split bf16 into hx[nxt] (row = batch cc, col = unit un)
            __nv_bfloat16 hi = __float2bfloat16(h);
            __nv_bfloat16 lo = __float2bfloat16(h - __bfloat162float(hi));
            char* hp = sm + OFF_B + nxt * 2 * BSECT + cc * BST + un * 2;
            *(__nv_bfloat16*)hp = hi;
            *(__nv_bfloat16*)(hp + BSECT) = lo;
            if (t == T_SZ - 1) ((float*)(sm + OFF_HFIN))[cc * 68 + un] = h;
        }

        // ---- commit x(t+1) ----
        if (hasNext) {
#pragma unroll
            for (int m = 0; m < 5; ++m) {
                if (xok[m]) {
                    float v = xv[m];
                    xptr[m] += IN_SZ;
                    if (xf[m] == 64) ((float*)(sm + OFF_X64))[nxt * 16 + xn[m]] = v;
                    else {
                        __nv_bfloat16 hi = __float2bfloat16(v);
                        __nv_bfloat16 lo = __float2bfloat16(v - __bfloat162float(hi));
                        char* bp = sm + OFF_B + nxt * 2 * BSECT + xn[m] * BST + (64 + xf[m]) * 2;
                        *(__nv_bfloat16*)bp = hi;
                        *(__nv_bfloat16*)(bp + BSECT) = lo;
                    }
                }
            }
        }
        __syncthreads();
    }

    // ---- FC head ----
    if (tid < BR * 7) {
        int rr = tid / 7, o = tid - rr * 7;
        float s = fcb[o];
        const float* wrow = fcW + o * H_SZ;
        const float* hf = (const float*)(sm + OFF_HFIN) + rr * 68;
#pragma unroll 8
        for (int u = 0; u < H_SZ; ++u) s += wrow[u] * hf[u];
        out[(size_t)(b0 + rr) * 7 + o] = sigf(s);
    }
}

extern "C" void kernel_launch(void* const* d_in, const int* in_sizes, int n_in,
                              void* d_out, int out_size) {
    const float* x    = (const float*)d_in[0];
    const float* Wih  = (const float*)d_in[1];
    const float* Whh  = (const float*)d_in[2];
    const float* bih  = (const float*)d_in[3];
    const float* bhh  = (const float*)d_in[4];
    const float* fcW  = (const float*)d_in[5];
    const float* fcb  = (const float*)d_in[6];
    float* out = (float*)d_out;

    cudaFuncSetAttribute(lstm_mma_kernel,
                         cudaFuncAttributeMaxDynamicSharedMemorySize, SMEM_TOTAL);
    lstm_mma_kernel<<<B_SZ / BR, NTH, SMEM_TOTAL>>>(x, Wih, Whh, bih, bhh, fcW, fcb, out);
}

// round 15
// speedup vs baseline: 1.6122x; 1.6122x over previous
#include <cuda_runtime.h>
#include <cuda_fp16.h>
#include <cstdint>

#define B_SZ 2048
#define T_SZ 256
#define IN_SZ 65
#define H_SZ 64
#define BR 16
#define NTH 256

typedef unsigned int u32;

// ---- smem layout (bytes) ----
#define AST 272                          // A row stride: 136 fp16 (16B-mult, LDSM conflict-free)
#define BST 272                          // hx row stride
#define OFF_A  0                         // A fp16 [256][AST] = 69632
#define OFF_B  69632                     // hx fp16 [par][16][BST]
#define BSECT  (16 * BST)                // 4352
#define OFF_X64 (OFF_B + 2 * BSECT)      // 78336: x64 [par][16] float = 128
#define OFF_HFIN (OFF_X64 + 128)         // hfin [16][68] float = 4352
#define SMEM_TOTAL (OFF_HFIN + 4352)     // 83072

__device__ __forceinline__ u32 smem_u32(const void* p) {
    u32 a;
    asm("{ .reg .u64 t; cvta.to.shared.u64 t, %1; cvt.u32.u64 %0, t; }" : "=r"(a) : "l"(p));
    return a;
}
__device__ __forceinline__ void ldsm4(u32& r0, u32& r1, u32& r2, u32& r3, u32 addr) {
    asm volatile("ldmatrix.sync.aligned.m8n8.x4.shared.b16 {%0,%1,%2,%3}, [%4];"
                 : "=r"(r0), "=r"(r1), "=r"(r2), "=r"(r3) : "r"(addr));
}
__device__ __forceinline__ void mma16816h(float* d, const u32* a, u32 b0, u32 b1) {
    asm volatile("mma.sync.aligned.m16n8k16.row.col.f32.f16.f16.f32 "
                 "{%0,%1,%2,%3}, {%4,%5,%6,%7}, {%8,%9}, {%0,%1,%2,%3};"
                 : "+f"(d[0]), "+f"(d[1]), "+f"(d[2]), "+f"(d[3])
                 : "r"(a[0]), "r"(a[1]), "r"(a[2]), "r"(a[3]), "r"(b0), "r"(b1));
}
__device__ __forceinline__ float ex2f(float x) { float y; asm("ex2.approx.f32 %0, %1;" : "=f"(y) : "f"(x)); return y; }
__device__ __forceinline__ float rcpf(float x) { float y; asm("rcp.approx.f32 %0, %1;" : "=f"(y) : "f"(x)); return y; }
__device__ __forceinline__ float sigf(float x) { return rcpf(1.0f + ex2f(-1.4426950408889634f * x)); }
__device__ __forceinline__ float tanhf_(float x) { return fmaf(2.0f, rcpf(1.0f + ex2f(-2.8853900817779268f * x)), -1.0f); }

__global__ __launch_bounds__(NTH, 1)
void lstm_mma_kernel(const float* __restrict__ x,
                     const float* __restrict__ Wih,
                     const float* __restrict__ Whh,
                     const float* __restrict__ bih,
                     const float* __restrict__ bhh,
                     const float* __restrict__ fcW,
                     const float* __restrict__ fcb,
                     float* __restrict__ out) {
    extern __shared__ char sm[];
    const u32 smb = smem_u32(sm);
    const int tid = threadIdx.x;
    const int wid = tid >> 5;
    const int lane = tid & 31;
    const int b0 = blockIdx.x * BR;

    // ---- one-time: W -> A tile (fp16). A row g, col k: k<64 = Whh, 64..127 = Wih[:,0:64]
    for (int idx = tid; idx < 256 * 128; idx += NTH) {
        int g = idx >> 7, k = idx & 127;
        float v = (k < 64) ? Whh[g * 64 + k] : Wih[g * 65 + (k - 64)];
        *(__half*)(sm + OFF_A + g * AST + k * 2) = __float2half_rn(v);
    }
    // zero hx buffers (h(-1)=0, padding) + x64
    for (int idx = tid; idx < (2 * BSECT) / 4; idx += NTH) ((u32*)(sm + OFF_B))[idx] = 0;
    if (tid < 32) ((float*)(sm + OFF_X64))[tid] = 0.0f;

    // ---- x-stream slots: 16 rows x 65 feats = 1040 -> 5 slots/thread
    const float* xptr[5]; int xn[5], xf[5]; bool xok[5];
#pragma unroll
    for (int m = 0; m < 5; ++m) {
        int idx = tid + m * NTH;
        xok[m] = idx < 16 * IN_SZ;
        int n = xok[m] ? idx / IN_SZ : 0;
        int f = xok[m] ? idx - n * IN_SZ : 0;
        xn[m] = n; xf[m] = f;
        xptr[m] = x + ((size_t)(b0 + n) * T_SZ) * IN_SZ + f;
    }
    __syncthreads();
    // x(0) -> parity 0
#pragma unroll
    for (int m = 0; m < 5; ++m) {
        if (xok[m]) {
            float v = *xptr[m];
            xptr[m] += IN_SZ;
            if (xf[m] == 64) ((float*)(sm + OFF_X64))[xn[m]] = v;
            else *(__half*)(sm + OFF_B + xn[m] * BST + (64 + xf[m]) * 2) = __float2half_rn(v);
        }
    }

    // ---- roles: warp w -> units 16*(w&3)..+15 (all 4 gate groups), batches (w>>2)*8..+7
    const int wq = wid & 3;
    const int nb = (wid >> 2) * 8;
    const int r = lane >> 2;
    const int u0 = wq * 16 + r, u1 = u0 + 8;
    const int c0 = nb + 2 * (lane & 3), c1 = c0 + 1;

    float bias[8], w64r[8];
#pragma unroll
    for (int G = 0; G < 4; ++G) {
        int ga = G * 64 + u0, gb_ = G * 64 + u1;
        bias[G * 2] = bih[ga] + bhh[ga];
        bias[G * 2 + 1] = bih[gb_] + bhh[gb_];
        w64r[G * 2] = Wih[ga * 65 + 64];
        w64r[G * 2 + 1] = Wih[gb_ * 65 + 64];
    }
    float cst[4] = {0.f, 0.f, 0.f, 0.f};   // cells (u0,c0),(u0,c1),(u1,c0),(u1,c1)

    // ldmatrix base: + G*64*AST + kt*32
    const u32 aBase = smb + OFF_A + (wq * 16 + (lane & 15)) * AST + (lane >> 4) * 16;
    // B frag base: row n = nb + lane/4, k-byte = (lane%4)*4 ; + par + kt*32 (b1 at +16)
    const u32 bBase = smb + OFF_B + (nb + (lane >> 2)) * BST + (lane & 3) * 4;

    __syncthreads();

    for (int t = 0; t < T_SZ; ++t) {
        const int par = t & 1, nxt = par ^ 1;
        const bool hasNext = (t + 1 < T_SZ);

        // ---- load B fragments (hx fp16) for this parity ----
        u32 bh[16];
        {
            const char* ph = (const char*)sm + (bBase - smb) + par * BSECT;
#pragma unroll
            for (int kt = 0; kt < 8; ++kt) {
                bh[2 * kt]     = *(const u32*)(ph + kt * 32);
                bh[2 * kt + 1] = *(const u32*)(ph + kt * 32 + 16);
            }
        }
        // ---- prefetch x(t+1) ----
        float xv[5];
#pragma unroll
        for (int m = 0; m < 5; ++m) xv[m] = (hasNext && xok[m]) ? *xptr[m] : 0.f;
        // x64 for this step
        const float xs0 = ((float*)(sm + OFF_X64))[par * 16 + c0];
        const float xs1 = ((float*)(sm + OFF_X64))[par * 16 + c1];

        // ---- MMA: single fp16 product, kt outer, G inner (4 chains of depth 8) ----
        float D[4][4];
#pragma unroll
        for (int G = 0; G < 4; ++G) { D[G][0] = D[G][1] = D[G][2] = D[G][3] = 0.f; }
#pragma unroll
        for (int kt = 0; kt < 8; ++kt) {
            const u32 bh0 = bh[2 * kt], bh1 = bh[2 * kt + 1];
#pragma unroll
            for (int G = 0; G < 4; ++G) {
                u32 a[4];
                ldsm4(a[0], a[1], a[2], a[3], aBase + G * 64 * AST + kt * 32);
                mma16816h(D[G], a, bh0, bh1);
            }
        }

        // ---- update (in registers): cells q: 0=(u0,c0) 1=(u0,c1) 2=(u1,c0) 3=(u1,c1) ----
#pragma unroll
        for (int q = 0; q < 4; ++q) {
            const int uu = (q >> 1);
            const float xs = (q & 1) ? xs1 : xs0;
            const int cc = (q & 1) ? c1 : c0;
            const int un = uu ? u1 : u0;
            float gi = D[0][q] + fmaf(w64r[0 + uu], xs, bias[0 + uu]);
            float gf = D[1][q] + fmaf(w64r[2 + uu], xs, bias[2 + uu]);
            float gg = D[2][q] + fmaf(w64r[4 + uu], xs, bias[4 + uu]);
            float go = D[3][q] + fmaf(w64r[6 + uu], xs, bias[6 + uu]);
            float iv = sigf(gi), fv = sigf(gf), gv = tanhf_(gg), ov = sigf(go);
            cst[q] = fv * cst[q] + iv * gv;
            float h = ov * tanhf_(cst[q]);
            *(__half*)(sm + OFF_B + nxt * BSECT + cc * BST + un * 2) = __float2half_rn(h);
            if (t == T_SZ - 1) ((float*)(sm + OFF_HFIN))[cc * 68 + un] = h;
        }

        // ---- commit x(t+1) ----
        if (hasNext) {
#pragma unroll
            for (int m = 0; m < 5; ++m) {
                if (xok[m]) {
                    float v = xv[m];
                    xptr[m] += IN_SZ;
                    if (xf[m] == 64) ((float*)(sm + OFF_X64))[nxt * 16 + xn[m]] = v;
                    else *(__half*)(sm + OFF_B + nxt * BSECT + xn[m] * BST + (64 + xf[m]) * 2) = __float2half_rn(v);
                }
            }
        }
        __syncthreads();
    }

    // ---- FC head ----
    if (tid < BR * 7) {
        int rr = tid / 7, o = tid - rr * 7;
        float s = fcb[o];
        const float* wrow = fcW + o * H_SZ;
        const float* hf = (const float*)(sm + OFF_HFIN) + rr * 68;
#pragma unroll 8
        for (int u = 0; u < H_SZ; ++u) s += wrow[u] * hf[u];
        out[(size_t)(b0 + rr) * 7 + o] = sigf(s);
    }
}

extern "C" void kernel_launch(void* const* d_in, const int* in_sizes, int n_in,
                              void* d_out, int out_size) {
    const float* x    = (const float*)d_in[0];
    const float* Wih  = (const float*)d_in[1];
    const float* Whh  = (const float*)d_in[2];
    const float* bih  = (const float*)d_in[3];
    const float* bhh  = (const float*)d_in[4];
    const float* fcW  = (const float*)d_in[5];
    const float* fcb  = (const float*)d_in[6];
    float* out = (float*)d_out;

    cudaFuncSetAttribute(lstm_mma_kernel,
                         cudaFuncAttributeMaxDynamicSharedMemorySize, SMEM_TOTAL);
    lstm_mma_kernel<<<B_SZ / BR, NTH, SMEM_TOTAL>>>(x, Wih, Whh, bih, bhh, fcW, fcb, out);
}

// round 16
// speedup vs baseline: 2.1763x; 1.3499x over previous
#include <cuda_runtime.h>
#include <cuda_fp16.h>
#include <cstdint>

#define B_SZ 2048
#define T_SZ 256
#define IN_SZ 65
#define H_SZ 64
#define BR 16
#define NTH 256

typedef unsigned int u32;

// ---- smem layout (bytes) ----
#define AST 272                          // A row stride: 136 fp16 (16B-mult, LDSM conflict-free)
#define BST 272                          // hx row stride
#define OFF_A  0                         // A fp16 [256][AST] = 69632 (used only at init)
#define OFF_B  69632                     // hx fp16 [par][16][BST]
#define BSECT  (16 * BST)                // 4352
#define OFF_X64 (OFF_B + 2 * BSECT)      // 78336: x64 [par][16] float = 128
#define OFF_HFIN (OFF_X64 + 128)         // hfin [16][68] float = 4352
#define SMEM_TOTAL (OFF_HFIN + 4352)     // 83072

__device__ __forceinline__ u32 smem_u32(const void* p) {
    u32 a;
    asm("{ .reg .u64 t; cvta.to.shared.u64 t, %1; cvt.u32.u64 %0, t; }" : "=r"(a) : "l"(p));
    return a;
}
__device__ __forceinline__ void ldsm4(u32& r0, u32& r1, u32& r2, u32& r3, u32 addr) {
    asm volatile("ldmatrix.sync.aligned.m8n8.x4.shared.b16 {%0,%1,%2,%3}, [%4];"
                 : "=r"(r0), "=r"(r1), "=r"(r2), "=r"(r3) : "r"(addr));
}
__device__ __forceinline__ void mma16816h(float* d, const u32* a, u32 b0, u32 b1) {
    asm volatile("mma.sync.aligned.m16n8k16.row.col.f32.f16.f16.f32 "
                 "{%0,%1,%2,%3}, {%4,%5,%6,%7}, {%8,%9}, {%0,%1,%2,%3};"
                 : "+f"(d[0]), "+f"(d[1]), "+f"(d[2]), "+f"(d[3])
                 : "r"(a[0]), "r"(a[1]), "r"(a[2]), "r"(a[3]), "r"(b0), "r"(b1));
}
__device__ __forceinline__ float ex2f(float x) { float y; asm("ex2.approx.f32 %0, %1;" : "=f"(y) : "f"(x)); return y; }
__device__ __forceinline__ float rcpf(float x) { float y; asm("rcp.approx.f32 %0, %1;" : "=f"(y) : "f"(x)); return y; }
__device__ __forceinline__ float sigf(float x) { return rcpf(1.0f + ex2f(-1.4426950408889634f * x)); }
__device__ __forceinline__ float tanhf_(float x) { return fmaf(2.0f, rcpf(1.0f + ex2f(-2.8853900817779268f * x)), -1.0f); }

__global__ __launch_bounds__(NTH, 1)
void lstm_mma_kernel(const float* __restrict__ x,
                     const float* __restrict__ Wih,
                     const float* __restrict__ Whh,
                     const float* __restrict__ bih,
                     const float* __restrict__ bhh,
                     const float* __restrict__ fcW,
                     const float* __restrict__ fcb,
                     float* __restrict__ out) {
    extern __shared__ char sm[];
    const u32 smb = smem_u32(sm);
    const int tid = threadIdx.x;
    const int wid = tid >> 5;
    const int lane = tid & 31;
    const int b0 = blockIdx.x * BR;

    // ---- one-time: W -> A smem tile (fp16). row g, col k: k<64 = Whh, 64..127 = Wih[:,0:64]
    for (int idx = tid; idx < 256 * 128; idx += NTH) {
        int g = idx >> 7, k = idx & 127;
        float v = (k < 64) ? Whh[g * 64 + k] : Wih[g * 65 + (k - 64)];
        *(__half*)(sm + OFF_A + g * AST + k * 2) = __float2half_rn(v);
    }
    // zero hx buffers (h(-1)=0, padding) + x64
    for (int idx = tid; idx < (2 * BSECT) / 4; idx += NTH) ((u32*)(sm + OFF_B))[idx] = 0;
    if (tid < 32) ((float*)(sm + OFF_X64))[tid] = 0.0f;

    // ---- x-stream slots: 16 rows x 65 feats = 1040 -> 5 slots/thread
    const float* xptr[5]; int xn[5], xf[5]; bool xok[5];
#pragma unroll
    for (int m = 0; m < 5; ++m) {
        int idx = tid + m * NTH;
        xok[m] = idx < 16 * IN_SZ;
        int n = xok[m] ? idx / IN_SZ : 0;
        int f = xok[m] ? idx - n * IN_SZ : 0;
        xn[m] = n; xf[m] = f;
        xptr[m] = x + ((size_t)(b0 + n) * T_SZ) * IN_SZ + f;
    }
    __syncthreads();
    // x(0) -> parity 0
#pragma unroll
    for (int m = 0; m < 5; ++m) {
        if (xok[m]) {
            float v = *xptr[m];
            xptr[m] += IN_SZ;
            if (xf[m] == 64) ((float*)(sm + OFF_X64))[xn[m]] = v;
            else *(__half*)(sm + OFF_B + xn[m] * BST + (64 + xf[m]) * 2) = __float2half_rn(v);
        }
    }

    // ---- roles: warp w -> units 16*(w&3)..+15 (all 4 gate groups), batches (w>>2)*8..+7
    const int wq = wid & 3;
    const int nb = (wid >> 2) * 8;
    const int r = lane >> 2;
    const int u0 = wq * 16 + r, u1 = u0 + 8;
    const int c0 = nb + 2 * (lane & 3), c1 = c0 + 1;

    float bias[8], w64r[8];
#pragma unroll
    for (int G = 0; G < 4; ++G) {
        int ga = G * 64 + u0, gb_ = G * 64 + u1;
        bias[G * 2] = bih[ga] + bhh[ga];
        bias[G * 2 + 1] = bih[gb_] + bhh[gb_];
        w64r[G * 2] = Wih[ga * 65 + 64];
        w64r[G * 2 + 1] = Wih[gb_ * 65 + 64];
    }
    float cst[4] = {0.f, 0.f, 0.f, 0.f};   // cells (u0,c0),(u0,c1),(u1,c0),(u1,c1)

    // ---- persist ALL A fragments in registers (constant across timesteps) ----
    const u32 aBase = smb + OFF_A + (wq * 16 + (lane & 15)) * AST + (lane >> 4) * 16;
    u32 afr[4][8][4];
#pragma unroll
    for (int G = 0; G < 4; ++G)
#pragma unroll
        for (int kt = 0; kt < 8; ++kt)
            ldsm4(afr[G][kt][0], afr[G][kt][1], afr[G][kt][2], afr[G][kt][3],
                  aBase + G * 64 * AST + kt * 32);

    // B frag base: row n = nb + lane/4, k-byte = (lane%4)*4 ; + par + kt*32 (b1 at +16)
    const u32 bBase = smb + OFF_B + (nb + (lane >> 2)) * BST + (lane & 3) * 4;

    __syncthreads();

    for (int t = 0; t < T_SZ; ++t) {
        const int par = t & 1, nxt = par ^ 1;
        const bool hasNext = (t + 1 < T_SZ);

        // ---- load B fragments (hx fp16) for this parity ----
        u32 bh[16];
        {
            const char* ph = (const char*)sm + (bBase - smb) + par * BSECT;
#pragma unroll
            for (int kt = 0; kt < 8; ++kt) {
                bh[2 * kt]     = *(const u32*)(ph + kt * 32);
                bh[2 * kt + 1] = *(const u32*)(ph + kt * 32 + 16);
            }
        }
        // ---- prefetch x(t+1) ----
        float xv[5];
#pragma unroll
        for (int m = 0; m < 5; ++m) xv[m] = (hasNext && xok[m]) ? *xptr[m] : 0.f;
        // x64 for this step
        const float xs0 = ((float*)(sm + OFF_X64))[par * 16 + c0];
        const float xs1 = ((float*)(sm + OFF_X64))[par * 16 + c1];

        // ---- MMA: pure register HMMA (A persistent, 4 chains of depth 8) ----
        float D[4][4];
#pragma unroll
        for (int G = 0; G < 4; ++G) { D[G][0] = D[G][1] = D[G][2] = D[G][3] = 0.f; }
#pragma unroll
        for (int kt = 0; kt < 8; ++kt) {
            const u32 bh0 = bh[2 * kt], bh1 = bh[2 * kt + 1];
#pragma unroll
            for (int G = 0; G < 4; ++G) {
                mma16816h(D[G], afr[G][kt], bh0, bh1);
            }
        }

        // ---- update (in registers): cells q: 0=(u0,c0) 1=(u0,c1) 2=(u1,c0) 3=(u1,c1) ----
#pragma unroll
        for (int q = 0; q < 4; ++q) {
            const int uu = (q >> 1);
            const float xs = (q & 1) ? xs1 : xs0;
            const int cc = (q & 1) ? c1 : c0;
            const int un = uu ? u1 : u0;
            float gi = D[0][q] + fmaf(w64r[0 + uu], xs, bias[0 + uu]);
            float gf = D[1][q] + fmaf(w64r[2 + uu], xs, bias[2 + uu]);
            float gg = D[2][q] + fmaf(w64r[4 + uu], xs, bias[4 + uu]);
            float go = D[3][q] + fmaf(w64r[6 + uu], xs, bias[6 + uu]);
            float iv = sigf(gi), fv = sigf(gf), gv = tanhf_(gg), ov = sigf(go);
            cst[q] = fv * cst[q] + iv * gv;
            float h = ov * tanhf_(cst[q]);
            *(__half*)(sm + OFF_B + nxt * BSECT + cc * BST + un * 2) = __float2half_rn(h);
            if (t == T_SZ - 1) ((float*)(sm + OFF_HFIN))[cc * 68 + un] = h;
        }

        // ---- commit x(t+1) ----
        if (hasNext) {
#pragma unroll
            for (int m = 0; m < 5; ++m) {
                if (xok[m]) {
                    float v = xv[m];
                    xptr[m] += IN_SZ;
                    if (xf[m] == 64) ((float*)(sm + OFF_X64))[nxt * 16 + xn[m]] = v;
                    else *(__half*)(sm + OFF_B + nxt * BSECT + xn[m] * BST + (64 + xf[m]) * 2) = __float2half_rn(v);
                }
            }
        }
        __syncthreads();
    }

    // ---- FC head ----
    if (tid < BR * 7) {
        int rr = tid / 7, o = tid - rr * 7;
        float s = fcb[o];
        const float* wrow = fcW + o * H_SZ;
        const float* hf = (const float*)(sm + OFF_HFIN) + rr * 68;
#pragma unroll 8
        for (int u = 0; u < H_SZ; ++u) s += wrow[u] * hf[u];
        out[(size_t)(b0 + rr) * 7 + o] = sigf(s);
    }
}

extern "C" void kernel_launch(void* const* d_in, const int* in_sizes, int n_in,
                              void* d_out, int out_size) {
    const float* x    = (const float*)d_in[0];
    const float* Wih  = (const float*)d_in[1];
    const float* Whh  = (const float*)d_in[2];
    const float* bih  = (const float*)d_in[3];
    const float* bhh  = (const float*)d_in[4];
    const float* fcW  = (const float*)d_in[5];
    const float* fcb  = (const float*)d_in[6];
    float* out = (float*)d_out;

    cudaFuncSetAttribute(lstm_mma_kernel,
                         cudaFuncAttributeMaxDynamicSharedMemorySize, SMEM_TOTAL);
    lstm_mma_kernel<<<B_SZ / BR, NTH, SMEM_TOTAL>>>(x, Wih, Whh, bih, bhh, fcW, fcb, out);
}

// round 17
// speedup vs baseline: 2.4441x; 1.1230x over previous
#include <cuda_runtime.h>
#include <cuda_fp16.h>
#include <cstdint>

#define B_SZ 2048
#define T_SZ 256
#define IN_SZ 65
#define H_SZ 64
#define BR 16
#define NTH 256

typedef unsigned int u32;

// ---- smem layout (bytes) ----
#define AST 272                          // A row stride: 136 fp16 (16B-mult, LDSM conflict-free)
#define BST 272                          // hx row stride
#define OFF_A  0                         // A fp16 [256][AST] = 69632 (used only at init)
#define OFF_B  69632                     // hx fp16 [par][16][BST]
#define BSECT  (16 * BST)                // 4352
#define OFF_X64 (OFF_B + 2 * BSECT)      // 78336: x64 [par][16] float = 128
#define OFF_HFIN (OFF_X64 + 128)         // hfin [16][68] float = 4352
#define SMEM_TOTAL (OFF_HFIN + 4352)     // 83072

__device__ __forceinline__ u32 smem_u32(const void* p) {
    u32 a;
    asm("{ .reg .u64 t; cvta.to.shared.u64 t, %1; cvt.u32.u64 %0, t; }" : "=r"(a) : "l"(p));
    return a;
}
__device__ __forceinline__ void ldsm4(u32& r0, u32& r1, u32& r2, u32& r3, u32 addr) {
    asm volatile("ldmatrix.sync.aligned.m8n8.x4.shared.b16 {%0,%1,%2,%3}, [%4];"
                 : "=r"(r0), "=r"(r1), "=r"(r2), "=r"(r3) : "r"(addr));
}
__device__ __forceinline__ void mma16816h(float* d, const u32* a, u32 b0, u32 b1) {
    asm volatile("mma.sync.aligned.m16n8k16.row.col.f32.f16.f16.f32 "
                 "{%0,%1,%2,%3}, {%4,%5,%6,%7}, {%8,%9}, {%0,%1,%2,%3};"
                 : "+f"(d[0]), "+f"(d[1]), "+f"(d[2]), "+f"(d[3])
                 : "r"(a[0]), "r"(a[1]), "r"(a[2]), "r"(a[3]), "r"(b0), "r"(b1));
}
__device__ __forceinline__ float ex2f(float x) { float y; asm("ex2.approx.f32 %0, %1;" : "=f"(y) : "f"(x)); return y; }
__device__ __forceinline__ float rcpf(float x) { float y; asm("rcp.approx.f32 %0, %1;" : "=f"(y) : "f"(x)); return y; }
__device__ __forceinline__ float sigf(float x) { return rcpf(1.0f + ex2f(-1.4426950408889634f * x)); }
// fast in-loop activations via MUFU.TANH
__device__ __forceinline__ float tanha(float x) { float y; asm("tanh.approx.f32 %0, %1;" : "=f"(y) : "f"(x)); return y; }
__device__ __forceinline__ float sigt(float x) { return fmaf(tanha(0.5f * x), 0.5f, 0.5f); }

// group barrier: ids 1,2 (0 reserved for __syncthreads), 128 threads each
#define GBAR(g) asm volatile("bar.sync %0, %1;" :: "r"((g) + 1), "r"(128) : "memory")

__global__ __launch_bounds__(NTH, 1)
void lstm_mma_kernel(const float* __restrict__ x,
                     const float* __restrict__ Wih,
                     const float* __restrict__ Whh,
                     const float* __restrict__ bih,
                     const float* __restrict__ bhh,
                     const float* __restrict__ fcW,
                     const float* __restrict__ fcb,
                     float* __restrict__ out) {
    extern __shared__ char sm[];
    const u32 smb = smem_u32(sm);
    const int tid = threadIdx.x;
    const int wid = tid >> 5;
    const int lane = tid & 31;
    const int b0 = blockIdx.x * BR;
    const int grp = wid >> 2;            // independent batch group (0: rows 0-7, 1: rows 8-15)

    // ---- one-time: W -> A smem tile (fp16). row g, col k: k<64 = Whh, 64..127 = Wih[:,0:64]
    for (int idx = tid; idx < 256 * 128; idx += NTH) {
        int g = idx >> 7, k = idx & 127;
        float v = (k < 64) ? Whh[g * 64 + k] : Wih[g * 65 + (k - 64)];
        *(__half*)(sm + OFF_A + g * AST + k * 2) = __float2half_rn(v);
    }
    // zero hx buffers (h(-1)=0, padding) + x64
    for (int idx = tid; idx < (2 * BSECT) / 4; idx += NTH) ((u32*)(sm + OFF_B))[idx] = 0;
    if (tid < 32) ((float*)(sm + OFF_X64))[tid] = 0.0f;

    // ---- x-stream slots, GROUP-LOCAL: each group's 128 threads own its 8 rows x 65 feats
    const int ltid = tid & 127;
    const float* xptr[5]; int xn[5], xf[5]; bool xok[5];
#pragma unroll
    for (int m = 0; m < 5; ++m) {
        int idx = ltid + m * 128;
        xok[m] = idx < 8 * IN_SZ;       // 520
        int nl = xok[m] ? idx / IN_SZ : 0;
        int f  = xok[m] ? idx - nl * IN_SZ : 0;
        xn[m] = grp * 8 + nl; xf[m] = f;
        xptr[m] = x + ((size_t)(b0 + xn[m]) * T_SZ) * IN_SZ + f;
    }
    __syncthreads();
    // x(0) -> parity 0
#pragma unroll
    for (int m = 0; m < 5; ++m) {
        if (xok[m]) {
            float v = *xptr[m];
            xptr[m] += IN_SZ;
            if (xf[m] == 64) ((float*)(sm + OFF_X64))[xn[m]] = v;
            else *(__half*)(sm + OFF_B + xn[m] * BST + (64 + xf[m]) * 2) = __float2half_rn(v);
        }
    }

    // ---- roles: warp w -> units 16*(w&3)..+15 (all 4 gate groups), batches grp*8..+7
    const int wq = wid & 3;
    const int nb = grp * 8;
    const int r = lane >> 2;
    const int u0 = wq * 16 + r, u1 = u0 + 8;
    const int c0 = nb + 2 * (lane & 3), c1 = c0 + 1;

    float bias[8], w64r[8];
#pragma unroll
    for (int G = 0; G < 4; ++G) {
        int ga = G * 64 + u0, gb_ = G * 64 + u1;
        bias[G * 2] = bih[ga] + bhh[ga];
        bias[G * 2 + 1] = bih[gb_] + bhh[gb_];
        w64r[G * 2] = Wih[ga * 65 + 64];
        w64r[G * 2 + 1] = Wih[gb_ * 65 + 64];
    }
    float cst[4] = {0.f, 0.f, 0.f, 0.f};   // cells (u0,c0),(u0,c1),(u1,c0),(u1,c1)

    // ---- persist ALL A fragments in registers (constant across timesteps) ----
    const u32 aBase = smb + OFF_A + (wq * 16 + (lane & 15)) * AST + (lane >> 4) * 16;
    u32 afr[4][8][4];
#pragma unroll
    for (int G = 0; G < 4; ++G)
#pragma unroll
        for (int kt = 0; kt < 8; ++kt)
            ldsm4(afr[G][kt][0], afr[G][kt][1], afr[G][kt][2], afr[G][kt][3],
                  aBase + G * 64 * AST + kt * 32);

    // B frag base: row n = nb + lane/4, k-byte = (lane%4)*4 ; + par + kt*32 (b1 at +16)
    const u32 bBase = smb + OFF_B + (nb + (lane >> 2)) * BST + (lane & 3) * 4;

    __syncthreads();

    for (int t = 0; t < T_SZ; ++t) {
        const int par = t & 1, nxt = par ^ 1;
        const bool hasNext = (t + 1 < T_SZ);

        // ---- load B fragments (hx fp16) for this parity ----
        u32 bh[16];
        {
            const char* ph = (const char*)sm + (bBase - smb) + par * BSECT;
#pragma unroll
            for (int kt = 0; kt < 8; ++kt) {
                bh[2 * kt]     = *(const u32*)(ph + kt * 32);
                bh[2 * kt + 1] = *(const u32*)(ph + kt * 32 + 16);
            }
        }
        // ---- prefetch x(t+1) ----
        float xv[5];
#pragma unroll
        for (int m = 0; m < 5; ++m) xv[m] = (hasNext && xok[m]) ? *xptr[m] : 0.f;
        // x64 for this step
        const float xs0 = ((float*)(sm + OFF_X64))[par * 16 + c0];
        const float xs1 = ((float*)(sm + OFF_X64))[par * 16 + c1];

        // ---- MMA: pure register HMMA (A persistent, 4 chains of depth 8) ----
        float D[4][4];
#pragma unroll
        for (int G = 0; G < 4; ++G) { D[G][0] = D[G][1] = D[G][2] = D[G][3] = 0.f; }
#pragma unroll
        for (int kt = 0; kt < 8; ++kt) {
            const u32 bh0 = bh[2 * kt], bh1 = bh[2 * kt + 1];
#pragma unroll
            for (int G = 0; G < 4; ++G) {
                mma16816h(D[G], afr[G][kt], bh0, bh1);
            }
        }

        // ---- update (in registers): cells q: 0=(u0,c0) 1=(u0,c1) 2=(u1,c0) 3=(u1,c1) ----
#pragma unroll
        for (int q = 0; q < 4; ++q) {
            const int uu = (q >> 1);
            const float xs = (q & 1) ? xs1 : xs0;
            const int cc = (q & 1) ? c1 : c0;
            const int un = uu ? u1 : u0;
            float gi = D[0][q] + fmaf(w64r[0 + uu], xs, bias[0 + uu]);
            float gf = D[1][q] + fmaf(w64r[2 + uu], xs, bias[2 + uu]);
            float gg = D[2][q] + fmaf(w64r[4 + uu], xs, bias[4 + uu]);
            float go = D[3][q] + fmaf(w64r[6 + uu], xs, bias[6 + uu]);
            float iv = sigt(gi), fv = sigt(gf), gv = tanha(gg), ov = sigt(go);
            cst[q] = fv * cst[q] + iv * gv;
            float h = ov * tanha(cst[q]);
            *(__half*)(sm + OFF_B + nxt * BSECT + cc * BST + un * 2) = __float2half_rn(h);
            if (t == T_SZ - 1) ((float*)(sm + OFF_HFIN))[cc * 68 + un] = h;
        }

        // ---- commit x(t+1) ----
        if (hasNext) {
#pragma unroll
            for (int m = 0; m < 5; ++m) {
                if (xok[m]) {
                    float v = xv[m];
                    xptr[m] += IN_SZ;
                    if (xf[m] == 64) ((float*)(sm + OFF_X64))[nxt * 16 + xn[m]] = v;
                    else *(__half*)(sm + OFF_B + nxt * BSECT + xn[m] * BST + (64 + xf[m]) * 2) = __float2half_rn(v);
                }
            }
        }
        GBAR(grp);     // group-local barrier: the two batch groups run independently
    }

    __syncthreads();   // join both groups before the FC head reads hfin

    // ---- FC head (accurate sigmoid) ----
    if (tid < BR * 7) {
        int rr = tid / 7, o = tid - rr * 7;
        float s = fcb[o];
        const float* wrow = fcW + o * H_SZ;
        const float* hf = (const float*)(sm + OFF_HFIN) + rr * 68;
#pragma unroll 8
        for (int u = 0; u < H_SZ; ++u) s += wrow[u] * hf[u];
        out[(size_t)(b0 + rr) * 7 + o] = sigf(s);
    }
}

extern "C" void kernel_launch(void* const* d_in, const int* in_sizes, int n_in,
                              void* d_out, int out_size) {
    const float* x    = (const float*)d_in[0];
    const float* Wih  = (const float*)d_in[1];
    const float* Whh  = (const float*)d_in[2];
    const float* bih  = (const float*)d_in[3];
    const float* bhh  = (const float*)d_in[4];
    const float* fcW  = (const float*)d_in[5];
    const float* fcb  = (const float*)d_in[6];
    float* out = (float*)d_out;

    cudaFuncSetAttribute(lstm_mma_kernel,
                         cudaFuncAttributeMaxDynamicSharedMemorySize, SMEM_TOTAL);
    lstm_mma_kernel<<<B_SZ / BR, NTH, SMEM_TOTAL>>>(x, Wih, Whh, bih, bhh, fcW, fcb, out);
}